// round 6
// baseline (speedup 1.0000x reference)
#include <cuda_runtime.h>
#include <math.h>
#include <stdint.h>

#define NB 4
#define LQ 5440
#define CC 256
#define HH_ 8
#define LL 4
#define PP 4
#define DD 32
#define LEN_IN 5440
#define M_TOT (NB * LQ)       // 21760
#define NQP 384               // fused qproj width: 256 offsets + 128 logits

// Scratch (device globals; no runtime allocation)
__device__ __align__(128) float g_value[NB * LEN_IN * CC];   // (n, s, h*d)
__device__ __align__(128) float g_qproj[NB * LQ * NQP];      // (n, q, [off|attn])
__device__ __align__(128) float g_mid[NB * LQ * CC];         // (n, q, h*d)
__device__ __align__(128) float g_wcomb[CC * NQP];           // packed [w_off | w_attn]
__device__ __align__(128) float g_bcomb[NQP];

// Level geometry (fixed by the problem's setup_inputs)
__device__ __constant__ int c_ww[LL] = {64, 32, 16, 8};
__device__ __constant__ int c_hh[LL] = {64, 32, 16, 8};
__device__ __constant__ int c_s0[LL] = {0, 4096, 5120, 5376};

__device__ __forceinline__ uint32_t f2tf32(float f) {
    uint32_t r;
    asm("cvt.rna.tf32.f32 %0, %1;" : "=r"(r) : "f"(f));
    return r;
}

// ---------------------------------------------------------------------------
// Pack [w_off | w_attn] -> g_wcomb, [b_off | b_attn] -> g_bcomb
// ---------------------------------------------------------------------------
__global__ void pack_kernel(const float* __restrict__ w_off,
                            const float* __restrict__ b_off,
                            const float* __restrict__ w_attn,
                            const float* __restrict__ b_attn)
{
    const int idx = blockIdx.x * blockDim.x + threadIdx.x;
    if (idx < CC * NQP) {
        const int k = idx / NQP;
        const int c = idx - k * NQP;
        g_wcomb[idx] = (c < 256) ? w_off[k * 256 + c] : w_attn[k * 128 + (c - 256)];
    }
    if (idx < NQP) {
        g_bcomb[idx] = (idx < 256) ? b_off[idx] : b_attn[idx - 256];
    }
}

// ---------------------------------------------------------------------------
// 3xTF32 error-compensated tensor-core GEMM + bias.
// C = A @ B + bias with a = a_hi + a_lo split; acc += ah*bh + ah*bl + al*bh.
// Block tile 128x128x16, 256 threads = 8 warps (4 m x 2 n).
// Warp tile 32x64 = 2 (m16) x 8 (n8) fragments of mma.sync.m16n8k8.tf32.
// ---------------------------------------------------------------------------
__global__ void __launch_bounds__(256, 2) gemm_3xtf32_kernel(
    const float* __restrict__ A, const float* __restrict__ B,
    const float* __restrict__ bias, float* __restrict__ Cout,
    int M, int Ncols, int K)
{
    __shared__ uint32_t AsH[16][132];   // [k][m] hi
    __shared__ uint32_t AsL[16][132];   // [k][m] lo
    __shared__ uint32_t BsH[16][132];   // [k][n] hi
    __shared__ uint32_t BsL[16][132];   // [k][n] lo

    const int t    = threadIdx.x;
    const int warp = t >> 5;
    const int lane = t & 31;
    const int g    = lane >> 2;        // groupID 0..7
    const int tig  = lane & 3;         // thread-in-group 0..3
    const int warp_m = warp & 3;       // 0..3 -> 32 rows each
    const int warp_n = warp >> 2;      // 0..1 -> 64 cols each
    const int m0 = blockIdx.y * 128;
    const int n0 = blockIdx.x * 128;

    float acc[2][8][4] = {};

    for (int k0 = 0; k0 < K; k0 += 16) {
        // Stage A: thread -> row am = t>>1, k-range ak..ak+7 (hi/lo split)
        {
            const int am = t >> 1;
            const int ak = (t & 1) * 8;
            const float* Ap = &A[(size_t)(m0 + am) * K + k0 + ak];
            #pragma unroll
            for (int j = 0; j < 2; j++) {
                float4 v = *reinterpret_cast<const float4*>(Ap + j * 4);
                const float* vv = reinterpret_cast<const float*>(&v);
                #pragma unroll
                for (int e = 0; e < 4; e++) {
                    const uint32_t hi = f2tf32(vv[e]);
                    const float hif = __uint_as_float(hi);
                    AsH[ak + j * 4 + e][am] = hi;
                    AsL[ak + j * 4 + e][am] = f2tf32(vv[e] - hif);
                }
            }
        }
        // Stage B: thread -> k row bk = t>>4, n-range bn..bn+7 (hi/lo split)
        {
            const int bk = t >> 4;
            const int bn = (t & 15) * 8;
            const float* Bp = &B[(size_t)(k0 + bk) * Ncols + n0 + bn];
            #pragma unroll
            for (int j = 0; j < 2; j++) {
                float4 v = *reinterpret_cast<const float4*>(Bp + j * 4);
                const float* vv = reinterpret_cast<const float*>(&v);
                #pragma unroll
                for (int e = 0; e < 4; e++) {
                    const uint32_t hi = f2tf32(vv[e]);
                    const float hif = __uint_as_float(hi);
                    BsH[bk][bn + j * 4 + e] = hi;
                    BsL[bk][bn + j * 4 + e] = f2tf32(vv[e] - hif);
                }
            }
        }
        __syncthreads();

        #pragma unroll
        for (int k8 = 0; k8 < 16; k8 += 8) {
            uint32_t aH[2][4], aL[2][4];
            #pragma unroll
            for (int mt = 0; mt < 2; mt++) {
                const int mb = warp_m * 32 + mt * 16;
                aH[mt][0] = AsH[k8 + tig][mb + g];
                aH[mt][1] = AsH[k8 + tig][mb + g + 8];
                aH[mt][2] = AsH[k8 + tig + 4][mb + g];
                aH[mt][3] = AsH[k8 + tig + 4][mb + g + 8];
                aL[mt][0] = AsL[k8 + tig][mb + g];
                aL[mt][1] = AsL[k8 + tig][mb + g + 8];
                aL[mt][2] = AsL[k8 + tig + 4][mb + g];
                aL[mt][3] = AsL[k8 + tig + 4][mb + g + 8];
            }
            #pragma unroll
            for (int nt = 0; nt < 8; nt++) {
                const int nb = warp_n * 64 + nt * 8 + g;
                const uint32_t bh0 = BsH[k8 + tig][nb];
                const uint32_t bh1 = BsH[k8 + tig + 4][nb];
                const uint32_t bl0 = BsL[k8 + tig][nb];
                const uint32_t bl1 = BsL[k8 + tig + 4][nb];
                #pragma unroll
                for (int mt = 0; mt < 2; mt++) {
                    // hi * hi
                    asm volatile(
                        "mma.sync.aligned.m16n8k8.row.col.f32.tf32.tf32.f32 "
                        "{%0,%1,%2,%3}, {%4,%5,%6,%7}, {%8,%9}, {%0,%1,%2,%3};"
                        : "+f"(acc[mt][nt][0]), "+f"(acc[mt][nt][1]),
                          "+f"(acc[mt][nt][2]), "+f"(acc[mt][nt][3])
                        : "r"(aH[mt][0]), "r"(aH[mt][1]),
                          "r"(aH[mt][2]), "r"(aH[mt][3]),
                          "r"(bh0), "r"(bh1));
                    // hi * lo
                    asm volatile(
                        "mma.sync.aligned.m16n8k8.row.col.f32.tf32.tf32.f32 "
                        "{%0,%1,%2,%3}, {%4,%5,%6,%7}, {%8,%9}, {%0,%1,%2,%3};"
                        : "+f"(acc[mt][nt][0]), "+f"(acc[mt][nt][1]),
                          "+f"(acc[mt][nt][2]), "+f"(acc[mt][nt][3])
                        : "r"(aH[mt][0]), "r"(aH[mt][1]),
                          "r"(aH[mt][2]), "r"(aH[mt][3]),
                          "r"(bl0), "r"(bl1));
                    // lo * hi
                    asm volatile(
                        "mma.sync.aligned.m16n8k8.row.col.f32.tf32.tf32.f32 "
                        "{%0,%1,%2,%3}, {%4,%5,%6,%7}, {%8,%9}, {%0,%1,%2,%3};"
                        : "+f"(acc[mt][nt][0]), "+f"(acc[mt][nt][1]),
                          "+f"(acc[mt][nt][2]), "+f"(acc[mt][nt][3])
                        : "r"(aL[mt][0]), "r"(aL[mt][1]),
                          "r"(aL[mt][2]), "r"(aL[mt][3]),
                          "r"(bh0), "r"(bh1));
                }
            }
        }
        __syncthreads();
    }

    // Epilogue: c0:(g,tig*2) c1:(g,tig*2+1) c2:(g+8,tig*2) c3:(g+8,tig*2+1)
    #pragma unroll
    for (int mt = 0; mt < 2; mt++) {
        const int row0 = m0 + warp_m * 32 + mt * 16 + g;
        #pragma unroll
        for (int nt = 0; nt < 8; nt++) {
            const int col = n0 + warp_n * 64 + nt * 8 + tig * 2;
            const float bx = bias[col], by = bias[col + 1];
            float2 r0, r1;
            r0.x = acc[mt][nt][0] + bx;  r0.y = acc[mt][nt][1] + by;
            r1.x = acc[mt][nt][2] + bx;  r1.y = acc[mt][nt][3] + by;
            *reinterpret_cast<float2*>(&Cout[(size_t)row0 * Ncols + col])       = r0;
            *reinterpret_cast<float2*>(&Cout[(size_t)(row0 + 8) * Ncols + col]) = r1;
        }
    }
}

// ---------------------------------------------------------------------------
// Fused softmax + bilinear sampling. One warp per (n, q, h).
// ---------------------------------------------------------------------------
__global__ void __launch_bounds__(256) sample_kernel(
    const float* __restrict__ refp)   // (N, LQ, L, 2)
{
    const unsigned F = 0xffffffffu;
    const int warp = (blockIdx.x * blockDim.x + threadIdx.x) >> 5;
    const int lane = threadIdx.x & 31;
    if (warp >= NB * LQ * HH_) return;

    const int h  = warp % HH_;
    const int nq = warp / HH_;        // n*LQ + q
    const int n  = nq / LQ;

    const float* __restrict__ qrow = &g_qproj[(size_t)nq * NQP];

    // --- softmax over 16 (l,p) logits (replicated in both half-warps) ---
    const float lg = qrow[256 + h * (LL * PP) + (lane & 15)];
    float mx = lg;
    #pragma unroll
    for (int s = 8; s >= 1; s >>= 1) mx = fmaxf(mx, __shfl_xor_sync(F, mx, s));
    const float e = __expf(lg - mx);
    float sm = e;
    #pragma unroll
    for (int s = 8; s >= 1; s >>= 1) sm += __shfl_xor_sync(F, sm, s);
    const float attn_v = e / sm;      // valid for tap (lane & 15)

    // --- per-lane slice of the 32 offset floats (l,p,xy) for this head ---
    const float offv = qrow[h * (LL * PP * 2) + lane];

    // --- phase 1: tap params for tap lp = lane & 15 ---
    const int lp = lane & 15;
    const int l  = lp >> 2;
    const float ox = __shfl_sync(F, offv, 2 * lp);
    const float oy = __shfl_sync(F, offv, 2 * lp + 1);

    const float* __restrict__ ref = &refp[(size_t)nq * (LL * 2)];
    const float lx = fminf(fmaxf(ref[l * 2 + 0] + ox, 0.0f), 1.0f);
    const float ly = fminf(fmaxf(ref[l * 2 + 1] + oy, 0.0f), 1.0f);

    const int ww = c_ww[l], hh = c_hh[l], s0 = c_s0[l];
    const float x = lx * (float)ww - 0.5f;
    const float y = ly * (float)hh - 0.5f;

    const int x0 = (int)floorf(x);
    const int y0 = (int)floorf(y);
    const int ix0 = min(max(x0, 0), ww - 1);
    const int ix1 = min(max(x0 + 1, 0), ww - 1);
    const int iy0 = min(max(y0, 0), hh - 1);
    const int iy1 = min(max(y0 + 1, 0), hh - 1);

    const float wxl = (float)ix1 - x;
    const float wxr = x - (float)ix0;
    const float wyt = (float)iy1 - y;
    const float wyb = y - (float)iy0;
    const float wA = attn_v * wxl * wyt;
    const float wB = attn_v * wxl * wyb;
    const float wC = attn_v * wxr * wyt;
    const float wD = attn_v * wxr * wyb;

    const int offA  = (n * LEN_IN + s0 + iy0 * ww + ix0) * CC + h * DD;
    const int rstep = (iy1 - iy0) * ww * CC;    // <= 16384, fits 16 bits
    const int cstep = (ix1 - ix0) * CC;         // 0 or 256
    const int steps = rstep | (cstep << 16);

    // --- phase 2: vectorized gather. g = tap group, c8 = channel quad ---
    const int g  = lane >> 3;
    const int c8 = lane & 7;
    float4 acc = make_float4(0.f, 0.f, 0.f, 0.f);

    #pragma unroll
    for (int b = 0; b < 4; b++) {
        const int src = b * 4 + g;              // tap index 0..15
        const int   o  = __shfl_sync(F, offA,  src);
        const int   st = __shfl_sync(F, steps, src);
        const float w0 = __shfl_sync(F, wA, src);
        const float w1 = __shfl_sync(F, wB, src);
        const float w2 = __shfl_sync(F, wC, src);
        const float w3 = __shfl_sync(F, wD, src);
        const int rs = st & 0xFFFF;
        const int cs = st >> 16;
        const float* __restrict__ p = &g_value[o + c8 * 4];
        const float4 va = *reinterpret_cast<const float4*>(p);
        const float4 vb = *reinterpret_cast<const float4*>(p + rs);
        const float4 vc = *reinterpret_cast<const float4*>(p + cs);
        const float4 vd = *reinterpret_cast<const float4*>(p + rs + cs);
        acc.x = fmaf(w0, va.x, fmaf(w1, vb.x, fmaf(w2, vc.x, fmaf(w3, vd.x, acc.x))));
        acc.y = fmaf(w0, va.y, fmaf(w1, vb.y, fmaf(w2, vc.y, fmaf(w3, vd.y, acc.y))));
        acc.z = fmaf(w0, va.z, fmaf(w1, vb.z, fmaf(w2, vc.z, fmaf(w3, vd.z, acc.z))));
        acc.w = fmaf(w0, va.w, fmaf(w1, vb.w, fmaf(w2, vc.w, fmaf(w3, vd.w, acc.w))));
    }

    // --- phase 3: reduce over the 4 tap groups ---
    #pragma unroll
    for (int s = 8; s <= 16; s <<= 1) {
        acc.x += __shfl_xor_sync(F, acc.x, s);
        acc.y += __shfl_xor_sync(F, acc.y, s);
        acc.z += __shfl_xor_sync(F, acc.z, s);
        acc.w += __shfl_xor_sync(F, acc.w, s);
    }

    if (lane < 8) {
        *reinterpret_cast<float4*>(&g_mid[(size_t)nq * CC + h * DD + c8 * 4]) = acc;
    }
}

// ---------------------------------------------------------------------------
// Launch
// ---------------------------------------------------------------------------
extern "C" void kernel_launch(void* const* d_in, const int* in_sizes, int n_in,
                              void* d_out, int out_size)
{
    const float* query   = (const float*)d_in[0];
    const float* refp    = (const float*)d_in[1];
    const float* in_flat = (const float*)d_in[2];
    // d_in[3] shapes, d_in[4] starts — fixed, baked into __constant__
    const float* w_off   = (const float*)d_in[5];
    const float* b_off   = (const float*)d_in[6];
    const float* w_attn  = (const float*)d_in[7];
    const float* b_attn  = (const float*)d_in[8];
    const float* w_val   = (const float*)d_in[9];
    const float* b_val   = (const float*)d_in[10];
    const float* w_out   = (const float*)d_in[11];
    const float* b_out   = (const float*)d_in[12];
    float* out = (float*)d_out;

    float *p_value, *p_qproj, *p_mid, *p_wcomb, *p_bcomb;
    cudaGetSymbolAddress((void**)&p_value, g_value);
    cudaGetSymbolAddress((void**)&p_qproj, g_qproj);
    cudaGetSymbolAddress((void**)&p_mid,   g_mid);
    cudaGetSymbolAddress((void**)&p_wcomb, g_wcomb);
    cudaGetSymbolAddress((void**)&p_bcomb, g_bcomb);

    const dim3 blk(256);

    // 0) pack fused qproj weights
    pack_kernel<<<(CC * NQP + 255) / 256, blk>>>(w_off, b_off, w_attn, b_attn);

    // 1) value projection: (21760 x 256) @ (256 x 256)
    gemm_3xtf32_kernel<<<dim3(CC / 128, M_TOT / 128), blk>>>(
        in_flat, w_val, b_val, p_value, M_TOT, CC, CC);

    // 2) fused query projection: (21760 x 256) @ (256 x 384)
    gemm_3xtf32_kernel<<<dim3(NQP / 128, M_TOT / 128), blk>>>(
        query, p_wcomb, p_bcomb, p_qproj, M_TOT, NQP, CC);

    // 3) fused softmax + bilinear sampling (one warp per (n,q,h))
    {
        const int warps = NB * LQ * HH_;           // 174080
        const int blocks = (warps * 32 + 255) / 256;
        sample_kernel<<<blocks, blk>>>(refp);
    }

    // 4) output projection: (21760 x 256) @ (256 x 256) -> d_out
    gemm_3xtf32_kernel<<<dim3(CC / 128, M_TOT / 128), blk>>>(
        p_mid, w_out, b_out, out, M_TOT, CC, CC);
}

// round 7
// speedup vs baseline: 1.1919x; 1.1919x over previous
#include <cuda_runtime.h>
#include <math.h>
#include <stdint.h>

#define NB 4
#define LQ 5440
#define CC 256
#define HH_ 8
#define LL 4
#define PP 4
#define DD 32
#define LEN_IN 5440
#define M_TOT (NB * LQ)       // 21760
#define NQP 384               // fused qproj width: 256 offsets + 128 logits

// GEMM smem geometry (K-tile 32, 2 stages)
#define A_ST 36               // padded row stride (floats) for A [m][36]
#define B_ST 136              // padded row stride (floats) for B [k][136]
#define A_SZ (128 * A_ST)     // 4608 floats
#define B_SZ (32 * B_ST)      // 4352 floats
#define STAGE_SZ (A_SZ + B_SZ)            // 8960 floats
#define GEMM_SMEM_BYTES (2 * STAGE_SZ * 4) // 71680 B

// Scratch (device globals; no runtime allocation)
__device__ __align__(128) float g_value[NB * LEN_IN * CC];   // (n, s, h*d)
__device__ __align__(128) float g_qproj[NB * LQ * NQP];      // (n, q, [off|attn])
__device__ __align__(128) float g_mid[NB * LQ * CC];         // (n, q, h*d)
__device__ __align__(128) float g_wcomb[CC * NQP];           // packed [w_off | w_attn]
__device__ __align__(128) float g_bcomb[NQP];

// Level geometry (fixed by the problem's setup_inputs)
__device__ __constant__ int c_ww[LL] = {64, 32, 16, 8};
__device__ __constant__ int c_hh[LL] = {64, 32, 16, 8};
__device__ __constant__ int c_s0[LL] = {0, 4096, 5120, 5376};

__device__ __forceinline__ uint32_t f2tf32(float f) {
    uint32_t r;
    asm("cvt.rna.tf32.f32 %0, %1;" : "=r"(r) : "f"(f));
    return r;
}
__device__ __forceinline__ void split_tf32(float v, uint32_t& hi, uint32_t& lo) {
    hi = f2tf32(v);
    lo = f2tf32(v - __uint_as_float(hi));
}
__device__ __forceinline__ uint32_t smem_u32(const void* p) {
    return (uint32_t)__cvta_generic_to_shared(p);
}
__device__ __forceinline__ void cp_async16(uint32_t saddr, const void* gptr) {
    asm volatile("cp.async.cg.shared.global [%0], [%1], 16;" :: "r"(saddr), "l"(gptr));
}
__device__ __forceinline__ void cp_commit() {
    asm volatile("cp.async.commit_group;");
}
template <int N>
__device__ __forceinline__ void cp_wait() {
    asm volatile("cp.async.wait_group %0;" :: "n"(N));
}

// ---------------------------------------------------------------------------
// Pack [w_off | w_attn] -> g_wcomb, [b_off | b_attn] -> g_bcomb
// ---------------------------------------------------------------------------
__global__ void pack_kernel(const float* __restrict__ w_off,
                            const float* __restrict__ b_off,
                            const float* __restrict__ w_attn,
                            const float* __restrict__ b_attn)
{
    const int idx = blockIdx.x * blockDim.x + threadIdx.x;
    if (idx < CC * NQP) {
        const int k = idx / NQP;
        const int c = idx - k * NQP;
        g_wcomb[idx] = (c < 256) ? w_off[k * 256 + c] : w_attn[k * 128 + (c - 256)];
    }
    if (idx < NQP) {
        g_bcomb[idx] = (idx < 256) ? b_off[idx] : b_attn[idx - 256];
    }
}

// ---------------------------------------------------------------------------
// 3xTF32 error-compensated tensor-core GEMM + bias, cp.async double-buffered.
// C = A @ B + bias with a = a_hi + a_lo split; acc += ah*bh + ah*bl + al*bh.
// Block tile 128x128x32, 256 threads = 8 warps (4 m x 2 n).
// Warp tile 32x64 = 2 (m16) x 8 (n8) fragments of mma.sync.m16n8k8.tf32.
// Raw fp32 tiles staged via cp.async; tf32 hi/lo split done in registers.
// ---------------------------------------------------------------------------
__global__ void __launch_bounds__(256, 2) gemm_3xtf32_kernel(
    const float* __restrict__ A, const float* __restrict__ B,
    const float* __restrict__ bias, float* __restrict__ Cout,
    int M, int Ncols, int K)
{
    extern __shared__ float sm[];

    const int t    = threadIdx.x;
    const int warp = t >> 5;
    const int lane = t & 31;
    const int g    = lane >> 2;        // groupID 0..7
    const int tig  = lane & 3;         // thread-in-group 0..3
    const int warp_m = warp & 3;       // 0..3 -> 32 rows each
    const int warp_n = warp >> 2;      // 0..1 -> 64 cols each
    const int m0 = blockIdx.y * 128;
    const int n0 = blockIdx.x * 128;

    float acc[2][8][4] = {};
    const int NT = K >> 5;             // K=256 -> 8 k-tiles of 32

    // ---- tile copy: raw fp32, A [128][36], B [32][136] ----
    auto copy_tile = [&](int kt, int s) {
        float* As = sm + s * STAGE_SZ;
        float* Bs = As + A_SZ;
        const int k0 = kt * 32;
        #pragma unroll
        for (int i = 0; i < 4; i++) {
            const int c = t + i * 256;
            // A: 128 rows x 8 float4-chunks
            {
                const int m = c >> 3, j = c & 7;
                cp_async16(smem_u32(&As[m * A_ST + j * 4]),
                           &A[(size_t)(m0 + m) * K + k0 + j * 4]);
            }
            // B: 32 k-rows x 32 float4-chunks
            {
                const int k = c >> 5, j = c & 31;
                cp_async16(smem_u32(&Bs[k * B_ST + j * 4]),
                           &B[(size_t)(k0 + k) * Ncols + n0 + j * 4]);
            }
        }
        cp_commit();
    };

    auto compute_stage = [&](int s) {
        const float* As = sm + s * STAGE_SZ;
        const float* Bs = As + A_SZ;
        #pragma unroll
        for (int k8 = 0; k8 < 32; k8 += 8) {
            uint32_t aH[2][4], aL[2][4];
            #pragma unroll
            for (int mt = 0; mt < 2; mt++) {
                const int mb = warp_m * 32 + mt * 16;
                const float r0 = As[(mb + g)     * A_ST + k8 + tig];
                const float r1 = As[(mb + g + 8) * A_ST + k8 + tig];
                const float r2 = As[(mb + g)     * A_ST + k8 + tig + 4];
                const float r3 = As[(mb + g + 8) * A_ST + k8 + tig + 4];
                split_tf32(r0, aH[mt][0], aL[mt][0]);
                split_tf32(r1, aH[mt][1], aL[mt][1]);
                split_tf32(r2, aH[mt][2], aL[mt][2]);
                split_tf32(r3, aH[mt][3], aL[mt][3]);
            }
            #pragma unroll
            for (int nt = 0; nt < 8; nt++) {
                const int nb = warp_n * 64 + nt * 8 + g;
                const float b0r = Bs[(k8 + tig)     * B_ST + nb];
                const float b1r = Bs[(k8 + tig + 4) * B_ST + nb];
                uint32_t bh0, bl0, bh1, bl1;
                split_tf32(b0r, bh0, bl0);
                split_tf32(b1r, bh1, bl1);
                #pragma unroll
                for (int mt = 0; mt < 2; mt++) {
                    asm volatile(
                        "mma.sync.aligned.m16n8k8.row.col.f32.tf32.tf32.f32 "
                        "{%0,%1,%2,%3}, {%4,%5,%6,%7}, {%8,%9}, {%0,%1,%2,%3};"
                        : "+f"(acc[mt][nt][0]), "+f"(acc[mt][nt][1]),
                          "+f"(acc[mt][nt][2]), "+f"(acc[mt][nt][3])
                        : "r"(aH[mt][0]), "r"(aH[mt][1]),
                          "r"(aH[mt][2]), "r"(aH[mt][3]),
                          "r"(bh0), "r"(bh1));
                    asm volatile(
                        "mma.sync.aligned.m16n8k8.row.col.f32.tf32.tf32.f32 "
                        "{%0,%1,%2,%3}, {%4,%5,%6,%7}, {%8,%9}, {%0,%1,%2,%3};"
                        : "+f"(acc[mt][nt][0]), "+f"(acc[mt][nt][1]),
                          "+f"(acc[mt][nt][2]), "+f"(acc[mt][nt][3])
                        : "r"(aH[mt][0]), "r"(aH[mt][1]),
                          "r"(aH[mt][2]), "r"(aH[mt][3]),
                          "r"(bl0), "r"(bl1));
                    asm volatile(
                        "mma.sync.aligned.m16n8k8.row.col.f32.tf32.tf32.f32 "
                        "{%0,%1,%2,%3}, {%4,%5,%6,%7}, {%8,%9}, {%0,%1,%2,%3};"
                        : "+f"(acc[mt][nt][0]), "+f"(acc[mt][nt][1]),
                          "+f"(acc[mt][nt][2]), "+f"(acc[mt][nt][3])
                        : "r"(aL[mt][0]), "r"(aL[mt][1]),
                          "r"(aL[mt][2]), "r"(aL[mt][3]),
                          "r"(bh0), "r"(bh1));
                }
            }
        }
    };

    // ---- 2-stage pipeline ----
    copy_tile(0, 0);
    for (int kt = 0; kt < NT; kt++) {
        const int s = kt & 1;
        if (kt + 1 < NT) {
            copy_tile(kt + 1, s ^ 1);
            cp_wait<1>();
        } else {
            cp_wait<0>();
        }
        __syncthreads();
        compute_stage(s);
        __syncthreads();
    }

    // Epilogue: c0:(g,tig*2) c1:(g,tig*2+1) c2:(g+8,tig*2) c3:(g+8,tig*2+1)
    #pragma unroll
    for (int mt = 0; mt < 2; mt++) {
        const int row0 = m0 + warp_m * 32 + mt * 16 + g;
        #pragma unroll
        for (int nt = 0; nt < 8; nt++) {
            const int col = n0 + warp_n * 64 + nt * 8 + tig * 2;
            const float bx = bias[col], by = bias[col + 1];
            float2 r0, r1;
            r0.x = acc[mt][nt][0] + bx;  r0.y = acc[mt][nt][1] + by;
            r1.x = acc[mt][nt][2] + bx;  r1.y = acc[mt][nt][3] + by;
            *reinterpret_cast<float2*>(&Cout[(size_t)row0 * Ncols + col])       = r0;
            *reinterpret_cast<float2*>(&Cout[(size_t)(row0 + 8) * Ncols + col]) = r1;
        }
    }
}

// ---------------------------------------------------------------------------
// Fused softmax + bilinear sampling. One warp per (n, q, h).
// ---------------------------------------------------------------------------
__global__ void __launch_bounds__(256, 8) sample_kernel(
    const float* __restrict__ refp)   // (N, LQ, L, 2)
{
    const unsigned F = 0xffffffffu;
    const int warp = (blockIdx.x * blockDim.x + threadIdx.x) >> 5;
    const int lane = threadIdx.x & 31;
    if (warp >= NB * LQ * HH_) return;

    const int h  = warp % HH_;
    const int nq = warp / HH_;        // n*LQ + q
    const int n  = nq / LQ;

    const float* __restrict__ qrow = &g_qproj[(size_t)nq * NQP];

    // --- softmax over 16 (l,p) logits (replicated in both half-warps) ---
    const float lg = qrow[256 + h * (LL * PP) + (lane & 15)];
    float mx = lg;
    #pragma unroll
    for (int s = 8; s >= 1; s >>= 1) mx = fmaxf(mx, __shfl_xor_sync(F, mx, s));
    const float e = __expf(lg - mx);
    float sm = e;
    #pragma unroll
    for (int s = 8; s >= 1; s >>= 1) sm += __shfl_xor_sync(F, sm, s);
    const float attn_v = e / sm;      // valid for tap (lane & 15)

    // --- per-lane slice of the 32 offset floats (l,p,xy) for this head ---
    const float offv = qrow[h * (LL * PP * 2) + lane];

    // --- phase 1: tap params for tap lp = lane & 15 ---
    const int lp = lane & 15;
    const int l  = lp >> 2;
    const float ox = __shfl_sync(F, offv, 2 * lp);
    const float oy = __shfl_sync(F, offv, 2 * lp + 1);

    const float* __restrict__ ref = &refp[(size_t)nq * (LL * 2)];
    const float lx = fminf(fmaxf(ref[l * 2 + 0] + ox, 0.0f), 1.0f);
    const float ly = fminf(fmaxf(ref[l * 2 + 1] + oy, 0.0f), 1.0f);

    const int ww = c_ww[l], hh = c_hh[l], s0 = c_s0[l];
    const float x = lx * (float)ww - 0.5f;
    const float y = ly * (float)hh - 0.5f;

    const int x0 = (int)floorf(x);
    const int y0 = (int)floorf(y);
    const int ix0 = min(max(x0, 0), ww - 1);
    const int ix1 = min(max(x0 + 1, 0), ww - 1);
    const int iy0 = min(max(y0, 0), hh - 1);
    const int iy1 = min(max(y0 + 1, 0), hh - 1);

    const float wxl = (float)ix1 - x;
    const float wxr = x - (float)ix0;
    const float wyt = (float)iy1 - y;
    const float wyb = y - (float)iy0;
    const float wA = attn_v * wxl * wyt;
    const float wB = attn_v * wxl * wyb;
    const float wC = attn_v * wxr * wyt;
    const float wD = attn_v * wxr * wyb;

    const int offA  = (n * LEN_IN + s0 + iy0 * ww + ix0) * CC + h * DD;
    const int rstep = (iy1 - iy0) * ww * CC;    // <= 16384, fits 16 bits
    const int cstep = (ix1 - ix0) * CC;         // 0 or 256
    const int steps = rstep | (cstep << 16);

    // --- phase 2: vectorized gather. g = tap group, c8 = channel quad ---
    const int g  = lane >> 3;
    const int c8 = lane & 7;
    float4 acc = make_float4(0.f, 0.f, 0.f, 0.f);

    #pragma unroll
    for (int b = 0; b < 4; b++) {
        const int src = b * 4 + g;              // tap index 0..15
        const int   o  = __shfl_sync(F, offA,  src);
        const int   st = __shfl_sync(F, steps, src);
        const float w0 = __shfl_sync(F, wA, src);
        const float w1 = __shfl_sync(F, wB, src);
        const float w2 = __shfl_sync(F, wC, src);
        const float w3 = __shfl_sync(F, wD, src);
        const int rs = st & 0xFFFF;
        const int cs = st >> 16;
        const float* __restrict__ p = &g_value[o + c8 * 4];
        const float4 va = *reinterpret_cast<const float4*>(p);
        const float4 vb = *reinterpret_cast<const float4*>(p + rs);
        const float4 vc = *reinterpret_cast<const float4*>(p + cs);
        const float4 vd = *reinterpret_cast<const float4*>(p + rs + cs);
        acc.x = fmaf(w0, va.x, fmaf(w1, vb.x, fmaf(w2, vc.x, fmaf(w3, vd.x, acc.x))));
        acc.y = fmaf(w0, va.y, fmaf(w1, vb.y, fmaf(w2, vc.y, fmaf(w3, vd.y, acc.y))));
        acc.z = fmaf(w0, va.z, fmaf(w1, vb.z, fmaf(w2, vc.z, fmaf(w3, vd.z, acc.z))));
        acc.w = fmaf(w0, va.w, fmaf(w1, vb.w, fmaf(w2, vc.w, fmaf(w3, vd.w, acc.w))));
    }

    // --- phase 3: reduce over the 4 tap groups ---
    #pragma unroll
    for (int s = 8; s <= 16; s <<= 1) {
        acc.x += __shfl_xor_sync(F, acc.x, s);
        acc.y += __shfl_xor_sync(F, acc.y, s);
        acc.z += __shfl_xor_sync(F, acc.z, s);
        acc.w += __shfl_xor_sync(F, acc.w, s);
    }

    if (lane < 8) {
        *reinterpret_cast<float4*>(&g_mid[(size_t)nq * CC + h * DD + c8 * 4]) = acc;
    }
}

// ---------------------------------------------------------------------------
// Launch
// ---------------------------------------------------------------------------
extern "C" void kernel_launch(void* const* d_in, const int* in_sizes, int n_in,
                              void* d_out, int out_size)
{
    const float* query   = (const float*)d_in[0];
    const float* refp    = (const float*)d_in[1];
    const float* in_flat = (const float*)d_in[2];
    // d_in[3] shapes, d_in[4] starts — fixed, baked into __constant__
    const float* w_off   = (const float*)d_in[5];
    const float* b_off   = (const float*)d_in[6];
    const float* w_attn  = (const float*)d_in[7];
    const float* b_attn  = (const float*)d_in[8];
    const float* w_val   = (const float*)d_in[9];
    const float* b_val   = (const float*)d_in[10];
    const float* w_out   = (const float*)d_in[11];
    const float* b_out   = (const float*)d_in[12];
    float* out = (float*)d_out;

    float *p_value, *p_qproj, *p_mid, *p_wcomb, *p_bcomb;
    cudaGetSymbolAddress((void**)&p_value, g_value);
    cudaGetSymbolAddress((void**)&p_qproj, g_qproj);
    cudaGetSymbolAddress((void**)&p_mid,   g_mid);
    cudaGetSymbolAddress((void**)&p_wcomb, g_wcomb);
    cudaGetSymbolAddress((void**)&p_bcomb, g_bcomb);

    static int smem_set = 0;
    if (!smem_set) {
        cudaFuncSetAttribute(gemm_3xtf32_kernel,
                             cudaFuncAttributeMaxDynamicSharedMemorySize,
                             GEMM_SMEM_BYTES);
        smem_set = 1;
    }

    const dim3 blk(256);

    // 0) pack fused qproj weights
    pack_kernel<<<(CC * NQP + 255) / 256, blk>>>(w_off, b_off, w_attn, b_attn);

    // 1) value projection: (21760 x 256) @ (256 x 256)
    gemm_3xtf32_kernel<<<dim3(CC / 128, M_TOT / 128), blk, GEMM_SMEM_BYTES>>>(
        in_flat, w_val, b_val, p_value, M_TOT, CC, CC);

    // 2) fused query projection: (21760 x 256) @ (256 x 384)
    gemm_3xtf32_kernel<<<dim3(NQP / 128, M_TOT / 128), blk, GEMM_SMEM_BYTES>>>(
        query, p_wcomb, p_bcomb, p_qproj, M_TOT, NQP, CC);

    // 3) fused softmax + bilinear sampling (one warp per (n,q,h))
    {
        const int warps = NB * LQ * HH_;           // 174080
        const int blocks = (warps * 32 + 255) / 256;
        sample_kernel<<<blocks, blk>>>(refp);
    }

    // 4) output projection: (21760 x 256) @ (256 x 256) -> d_out
    gemm_3xtf32_kernel<<<dim3(CC / 128, M_TOT / 128), blk, GEMM_SMEM_BYTES>>>(
        p_mid, w_out, b_out, out, M_TOT, CC, CC);
}

// round 8
// speedup vs baseline: 1.1990x; 1.0059x over previous
#include <cuda_runtime.h>
#include <math.h>
#include <stdint.h>

#define NB 4
#define LQ 5440
#define CC 256
#define HH_ 8
#define LL 4
#define PP 4
#define DD 32
#define LEN_IN 5440
#define M_TOT (NB * LQ)       // 21760
#define NQP 384               // fused qproj width: 256 offsets + 128 logits

// GEMM smem geometry (K-tile 32, 2 stages)
#define A_ST 36               // padded row stride (floats) for A [m][36]
#define B_ST 136              // padded row stride (floats) for B [k][136]
#define A_SZ (128 * A_ST)     // 4608 floats
#define B_SZ (32 * B_ST)      // 4352 floats
#define STAGE_SZ (A_SZ + B_SZ)            // 8960 floats
#define GEMM_SMEM_BYTES (2 * STAGE_SZ * 4) // 71680 B

// Scratch (device globals; no runtime allocation)
__device__ __align__(128) float g_value[NB * LEN_IN * CC];   // (n, s, h*d)
__device__ __align__(128) float g_qproj[NB * LQ * NQP];      // (n, q, [off|attn])
__device__ __align__(128) float g_mid[NB * LQ * CC];         // (n, q, h*d)
__device__ __align__(128) float g_wcomb[CC * NQP];           // packed [w_off | w_attn]
__device__ __align__(128) float g_bcomb[NQP];

// Level geometry (fixed by the problem's setup_inputs)
__device__ __constant__ int c_ww[LL] = {64, 32, 16, 8};
__device__ __constant__ int c_hh[LL] = {64, 32, 16, 8};
__device__ __constant__ int c_s0[LL] = {0, 4096, 5120, 5376};

__device__ __forceinline__ uint32_t f2tf32(float f) {
    uint32_t r;
    asm("cvt.rna.tf32.f32 %0, %1;" : "=r"(r) : "f"(f));
    return r;
}
__device__ __forceinline__ void split_tf32(float v, uint32_t& hi, uint32_t& lo) {
    hi = f2tf32(v);
    lo = f2tf32(v - __uint_as_float(hi));
}
__device__ __forceinline__ uint32_t smem_u32(const void* p) {
    return (uint32_t)__cvta_generic_to_shared(p);
}
__device__ __forceinline__ void cp_async16(uint32_t saddr, const void* gptr) {
    asm volatile("cp.async.cg.shared.global [%0], [%1], 16;" :: "r"(saddr), "l"(gptr));
}
__device__ __forceinline__ void cp_commit() {
    asm volatile("cp.async.commit_group;");
}
template <int N>
__device__ __forceinline__ void cp_wait() {
    asm volatile("cp.async.wait_group %0;" :: "n"(N));
}

// ---------------------------------------------------------------------------
// Pack [w_off | w_attn] -> g_wcomb, [b_off | b_attn] -> g_bcomb
// ---------------------------------------------------------------------------
__global__ void pack_kernel(const float* __restrict__ w_off,
                            const float* __restrict__ b_off,
                            const float* __restrict__ w_attn,
                            const float* __restrict__ b_attn)
{
    const int idx = blockIdx.x * blockDim.x + threadIdx.x;
    if (idx < CC * NQP) {
        const int k = idx / NQP;
        const int c = idx - k * NQP;
        g_wcomb[idx] = (c < 256) ? w_off[k * 256 + c] : w_attn[k * 128 + (c - 256)];
    }
    if (idx < NQP) {
        g_bcomb[idx] = (idx < 256) ? b_off[idx] : b_attn[idx - 256];
    }
}

// ---------------------------------------------------------------------------
// 3xTF32 error-compensated tensor-core GEMM + bias, cp.async double-buffered.
// C = A @ B + bias with a = a_hi + a_lo split; acc += ah*bh + ah*bl + al*bh.
// Block tile 128x128x32, 256 threads = 8 warps (4 m x 2 n).
// Warp tile 32x64 = 2 (m16) x 8 (n8) fragments of mma.sync.m16n8k8.tf32.
// Raw fp32 tiles staged via cp.async; tf32 hi/lo split done in registers.
// ---------------------------------------------------------------------------
__global__ void __launch_bounds__(256, 2) gemm_3xtf32_kernel(
    const float* __restrict__ A, const float* __restrict__ B,
    const float* __restrict__ bias, float* __restrict__ Cout,
    int M, int Ncols, int K)
{
    extern __shared__ float sm[];

    const int t    = threadIdx.x;
    const int warp = t >> 5;
    const int lane = t & 31;
    const int g    = lane >> 2;        // groupID 0..7
    const int tig  = lane & 3;         // thread-in-group 0..3
    const int warp_m = warp & 3;       // 0..3 -> 32 rows each
    const int warp_n = warp >> 2;      // 0..1 -> 64 cols each
    const int m0 = blockIdx.y * 128;
    const int n0 = blockIdx.x * 128;

    float acc[2][8][4] = {};
    const int NT = K >> 5;             // K=256 -> 8 k-tiles of 32

    // ---- tile copy: raw fp32, A [128][36], B [32][136] ----
    auto copy_tile = [&](int kt, int s) {
        float* As = sm + s * STAGE_SZ;
        float* Bs = As + A_SZ;
        const int k0 = kt * 32;
        #pragma unroll
        for (int i = 0; i < 4; i++) {
            const int c = t + i * 256;
            // A: 128 rows x 8 float4-chunks
            {
                const int m = c >> 3, j = c & 7;
                cp_async16(smem_u32(&As[m * A_ST + j * 4]),
                           &A[(size_t)(m0 + m) * K + k0 + j * 4]);
            }
            // B: 32 k-rows x 32 float4-chunks
            {
                const int k = c >> 5, j = c & 31;
                cp_async16(smem_u32(&Bs[k * B_ST + j * 4]),
                           &B[(size_t)(k0 + k) * Ncols + n0 + j * 4]);
            }
        }
        cp_commit();
    };

    auto compute_stage = [&](int s) {
        const float* As = sm + s * STAGE_SZ;
        const float* Bs = As + A_SZ;
        #pragma unroll
        for (int k8 = 0; k8 < 32; k8 += 8) {
            uint32_t aH[2][4], aL[2][4];
            #pragma unroll
            for (int mt = 0; mt < 2; mt++) {
                const int mb = warp_m * 32 + mt * 16;
                const float r0 = As[(mb + g)     * A_ST + k8 + tig];
                const float r1 = As[(mb + g + 8) * A_ST + k8 + tig];
                const float r2 = As[(mb + g)     * A_ST + k8 + tig + 4];
                const float r3 = As[(mb + g + 8) * A_ST + k8 + tig + 4];
                split_tf32(r0, aH[mt][0], aL[mt][0]);
                split_tf32(r1, aH[mt][1], aL[mt][1]);
                split_tf32(r2, aH[mt][2], aL[mt][2]);
                split_tf32(r3, aH[mt][3], aL[mt][3]);
            }
            #pragma unroll
            for (int nt = 0; nt < 8; nt++) {
                const int nb = warp_n * 64 + nt * 8 + g;
                const float b0r = Bs[(k8 + tig)     * B_ST + nb];
                const float b1r = Bs[(k8 + tig + 4) * B_ST + nb];
                uint32_t bh0, bl0, bh1, bl1;
                split_tf32(b0r, bh0, bl0);
                split_tf32(b1r, bh1, bl1);
                #pragma unroll
                for (int mt = 0; mt < 2; mt++) {
                    asm volatile(
                        "mma.sync.aligned.m16n8k8.row.col.f32.tf32.tf32.f32 "
                        "{%0,%1,%2,%3}, {%4,%5,%6,%7}, {%8,%9}, {%0,%1,%2,%3};"
                        : "+f"(acc[mt][nt][0]), "+f"(acc[mt][nt][1]),
                          "+f"(acc[mt][nt][2]), "+f"(acc[mt][nt][3])
                        : "r"(aH[mt][0]), "r"(aH[mt][1]),
                          "r"(aH[mt][2]), "r"(aH[mt][3]),
                          "r"(bh0), "r"(bh1));
                    asm volatile(
                        "mma.sync.aligned.m16n8k8.row.col.f32.tf32.tf32.f32 "
                        "{%0,%1,%2,%3}, {%4,%5,%6,%7}, {%8,%9}, {%0,%1,%2,%3};"
                        : "+f"(acc[mt][nt][0]), "+f"(acc[mt][nt][1]),
                          "+f"(acc[mt][nt][2]), "+f"(acc[mt][nt][3])
                        : "r"(aH[mt][0]), "r"(aH[mt][1]),
                          "r"(aH[mt][2]), "r"(aH[mt][3]),
                          "r"(bl0), "r"(bl1));
                    asm volatile(
                        "mma.sync.aligned.m16n8k8.row.col.f32.tf32.tf32.f32 "
                        "{%0,%1,%2,%3}, {%4,%5,%6,%7}, {%8,%9}, {%0,%1,%2,%3};"
                        : "+f"(acc[mt][nt][0]), "+f"(acc[mt][nt][1]),
                          "+f"(acc[mt][nt][2]), "+f"(acc[mt][nt][3])
                        : "r"(aL[mt][0]), "r"(aL[mt][1]),
                          "r"(aL[mt][2]), "r"(aL[mt][3]),
                          "r"(bh0), "r"(bh1));
                }
            }
        }
    };

    // ---- 2-stage pipeline ----
    copy_tile(0, 0);
    for (int kt = 0; kt < NT; kt++) {
        const int s = kt & 1;
        if (kt + 1 < NT) {
            copy_tile(kt + 1, s ^ 1);
            cp_wait<1>();
        } else {
            cp_wait<0>();
        }
        __syncthreads();
        compute_stage(s);
        __syncthreads();
    }

    // Epilogue: c0:(g,tig*2) c1:(g,tig*2+1) c2:(g+8,tig*2) c3:(g+8,tig*2+1)
    #pragma unroll
    for (int mt = 0; mt < 2; mt++) {
        const int row0 = m0 + warp_m * 32 + mt * 16 + g;
        #pragma unroll
        for (int nt = 0; nt < 8; nt++) {
            const int col = n0 + warp_n * 64 + nt * 8 + tig * 2;
            const float bx = bias[col], by = bias[col + 1];
            float2 r0, r1;
            r0.x = acc[mt][nt][0] + bx;  r0.y = acc[mt][nt][1] + by;
            r1.x = acc[mt][nt][2] + bx;  r1.y = acc[mt][nt][3] + by;
            *reinterpret_cast<float2*>(&Cout[(size_t)row0 * Ncols + col])       = r0;
            *reinterpret_cast<float2*>(&Cout[(size_t)(row0 + 8) * Ncols + col]) = r1;
        }
    }
}

// ---------------------------------------------------------------------------
// Fused softmax + bilinear sampling. One warp per (n, q, h).
// ---------------------------------------------------------------------------
__global__ void __launch_bounds__(256, 8) sample_kernel(
    const float* __restrict__ refp)   // (N, LQ, L, 2)
{
    const unsigned F = 0xffffffffu;
    const int warp = (blockIdx.x * blockDim.x + threadIdx.x) >> 5;
    const int lane = threadIdx.x & 31;
    if (warp >= NB * LQ * HH_) return;

    const int h  = warp % HH_;
    const int nq = warp / HH_;        // n*LQ + q
    const int n  = nq / LQ;

    const float* __restrict__ qrow = &g_qproj[(size_t)nq * NQP];

    // --- softmax over 16 (l,p) logits (replicated in both half-warps) ---
    const float lg = qrow[256 + h * (LL * PP) + (lane & 15)];
    float mx = lg;
    #pragma unroll
    for (int s = 8; s >= 1; s >>= 1) mx = fmaxf(mx, __shfl_xor_sync(F, mx, s));
    const float e = __expf(lg - mx);
    float sm = e;
    #pragma unroll
    for (int s = 8; s >= 1; s >>= 1) sm += __shfl_xor_sync(F, sm, s);
    const float attn_v = e / sm;      // valid for tap (lane & 15)

    // --- per-lane slice of the 32 offset floats (l,p,xy) for this head ---
    const float offv = qrow[h * (LL * PP * 2) + lane];

    // --- phase 1: tap params for tap lp = lane & 15 ---
    const int lp = lane & 15;
    const int l  = lp >> 2;
    const float ox = __shfl_sync(F, offv, 2 * lp);
    const float oy = __shfl_sync(F, offv, 2 * lp + 1);

    const float* __restrict__ ref = &refp[(size_t)nq * (LL * 2)];
    const float lx = fminf(fmaxf(ref[l * 2 + 0] + ox, 0.0f), 1.0f);
    const float ly = fminf(fmaxf(ref[l * 2 + 1] + oy, 0.0f), 1.0f);

    const int ww = c_ww[l], hh = c_hh[l], s0 = c_s0[l];
    const float x = lx * (float)ww - 0.5f;
    const float y = ly * (float)hh - 0.5f;

    const int x0 = (int)floorf(x);
    const int y0 = (int)floorf(y);
    const int ix0 = min(max(x0, 0), ww - 1);
    const int ix1 = min(max(x0 + 1, 0), ww - 1);
    const int iy0 = min(max(y0, 0), hh - 1);
    const int iy1 = min(max(y0 + 1, 0), hh - 1);

    const float wxl = (float)ix1 - x;
    const float wxr = x - (float)ix0;
    const float wyt = (float)iy1 - y;
    const float wyb = y - (float)iy0;
    const float wA = attn_v * wxl * wyt;
    const float wB = attn_v * wxl * wyb;
    const float wC = attn_v * wxr * wyt;
    const float wD = attn_v * wxr * wyb;

    const int offA  = (n * LEN_IN + s0 + iy0 * ww + ix0) * CC + h * DD;
    const int rstep = (iy1 - iy0) * ww * CC;    // <= 16384, fits 16 bits
    const int cstep = (ix1 - ix0) * CC;         // 0 or 256
    const int steps = rstep | (cstep << 16);

    // --- phase 2: vectorized gather. g = tap group, c8 = channel quad ---
    const int g  = lane >> 3;
    const int c8 = lane & 7;
    float4 acc = make_float4(0.f, 0.f, 0.f, 0.f);

    #pragma unroll
    for (int b = 0; b < 4; b++) {
        const int src = b * 4 + g;              // tap index 0..15
        const int   o  = __shfl_sync(F, offA,  src);
        const int   st = __shfl_sync(F, steps, src);
        const float w0 = __shfl_sync(F, wA, src);
        const float w1 = __shfl_sync(F, wB, src);
        const float w2 = __shfl_sync(F, wC, src);
        const float w3 = __shfl_sync(F, wD, src);
        const int rs = st & 0xFFFF;
        const int cs = st >> 16;
        const float* __restrict__ p = &g_value[o + c8 * 4];
        const float4 va = *reinterpret_cast<const float4*>(p);
        const float4 vb = *reinterpret_cast<const float4*>(p + rs);
        const float4 vc = *reinterpret_cast<const float4*>(p + cs);
        const float4 vd = *reinterpret_cast<const float4*>(p + rs + cs);
        acc.x = fmaf(w0, va.x, fmaf(w1, vb.x, fmaf(w2, vc.x, fmaf(w3, vd.x, acc.x))));
        acc.y = fmaf(w0, va.y, fmaf(w1, vb.y, fmaf(w2, vc.y, fmaf(w3, vd.y, acc.y))));
        acc.z = fmaf(w0, va.z, fmaf(w1, vb.z, fmaf(w2, vc.z, fmaf(w3, vd.z, acc.z))));
        acc.w = fmaf(w0, va.w, fmaf(w1, vb.w, fmaf(w2, vc.w, fmaf(w3, vd.w, acc.w))));
    }

    // --- phase 3: reduce over the 4 tap groups ---
    #pragma unroll
    for (int s = 8; s <= 16; s <<= 1) {
        acc.x += __shfl_xor_sync(F, acc.x, s);
        acc.y += __shfl_xor_sync(F, acc.y, s);
        acc.z += __shfl_xor_sync(F, acc.z, s);
        acc.w += __shfl_xor_sync(F, acc.w, s);
    }

    if (lane < 8) {
        *reinterpret_cast<float4*>(&g_mid[(size_t)nq * CC + h * DD + c8 * 4]) = acc;
    }
}

// ---------------------------------------------------------------------------
// Launch
// ---------------------------------------------------------------------------
extern "C" void kernel_launch(void* const* d_in, const int* in_sizes, int n_in,
                              void* d_out, int out_size)
{
    const float* query   = (const float*)d_in[0];
    const float* refp    = (const float*)d_in[1];
    const float* in_flat = (const float*)d_in[2];
    // d_in[3] shapes, d_in[4] starts — fixed, baked into __constant__
    const float* w_off   = (const float*)d_in[5];
    const float* b_off   = (const float*)d_in[6];
    const float* w_attn  = (const float*)d_in[7];
    const float* b_attn  = (const float*)d_in[8];
    const float* w_val   = (const float*)d_in[9];
    const float* b_val   = (const float*)d_in[10];
    const float* w_out   = (const float*)d_in[11];
    const float* b_out   = (const float*)d_in[12];
    float* out = (float*)d_out;

    float *p_value, *p_qproj, *p_mid, *p_wcomb, *p_bcomb;
    cudaGetSymbolAddress((void**)&p_value, g_value);
    cudaGetSymbolAddress((void**)&p_qproj, g_qproj);
    cudaGetSymbolAddress((void**)&p_mid,   g_mid);
    cudaGetSymbolAddress((void**)&p_wcomb, g_wcomb);
    cudaGetSymbolAddress((void**)&p_bcomb, g_bcomb);

    static int smem_set = 0;
    if (!smem_set) {
        cudaFuncSetAttribute(gemm_3xtf32_kernel,
                             cudaFuncAttributeMaxDynamicSharedMemorySize,
                             GEMM_SMEM_BYTES);
        smem_set = 1;
    }

    const dim3 blk(256);

    // 0) pack fused qproj weights
    pack_kernel<<<(CC * NQP + 255) / 256, blk>>>(w_off, b_off, w_attn, b_attn);

    // 1) value projection: (21760 x 256) @ (256 x 256)
    gemm_3xtf32_kernel<<<dim3(CC / 128, M_TOT / 128), blk, GEMM_SMEM_BYTES>>>(
        in_flat, w_val, b_val, p_value, M_TOT, CC, CC);

    // 2) fused query projection: (21760 x 256) @ (256 x 384)
    gemm_3xtf32_kernel<<<dim3(NQP / 128, M_TOT / 128), blk, GEMM_SMEM_BYTES>>>(
        query, p_wcomb, p_bcomb, p_qproj, M_TOT, NQP, CC);

    // 3) fused softmax + bilinear sampling (one warp per (n,q,h))
    {
        const int warps = NB * LQ * HH_;           // 174080
        const int blocks = (warps * 32 + 255) / 256;
        sample_kernel<<<blocks, blk>>>(refp);
    }

    // 4) output projection: (21760 x 256) @ (256 x 256) -> d_out
    gemm_3xtf32_kernel<<<dim3(CC / 128, M_TOT / 128), blk, GEMM_SMEM_BYTES>>>(
        p_mid, w_out, b_out, out, M_TOT, CC, CC);
}